// round 15
// baseline (speedup 1.0000x reference)
#include <cuda_runtime.h>
#include <math.h>

// PQLayer forward, fully fused (R15 = R11 body EXACTLY, 1-warp blocks):
//   per (b,m): k* = argmax_k <x[b,m*8:+8], C[m,k,:]>
//   codes[b,m,:] = one_hot(k*)   (exact forward value of straight-through)
//   xhat[b,m*8:+8] = C[m,k*,:]
//
// R15 vs R11 (206.6us proven): ONLY the launch shape changes. 32-thr blocks:
// 96 regs x 32 thr = 3072 regs/block -> 21 blocks/SM = 21 warps (vs 20).
// launch_bounds(32,21) budget = 97 regs >= the kernel's 96, so no spill
// (R13's 11x64 config demanded 93 and spilled the cc cache -> 289us).
// Loop body, dot order, reduction, store sequence byte-identical to R11.

#define Bn    16384
#define FEAT  512
#define Mn    64
#define Kn    256
#define Dn    8
#define RPW   32
#define TILEB 32              // 32 rows per block (one warp)

typedef unsigned long long u64;
typedef unsigned int u32;

__device__ __forceinline__ u64 pack2(float lo, float hi) {
    u64 r; asm("mov.b64 %0, {%1,%2};" : "=l"(r) : "f"(lo), "f"(hi)); return r;
}
__device__ __forceinline__ void unpack2(u64 v, float& lo, float& hi) {
    asm("mov.b64 {%0,%1}, %2;" : "=f"(lo), "=f"(hi) : "l"(v));
}
__device__ __forceinline__ u64 fma2(u64 a, u64 b, u64 c) {
    u64 d; asm("fma.rn.f32x2 %0, %1, %2, %3;" : "=l"(d) : "l"(a), "l"(b), "l"(c)); return d;
}
__device__ __forceinline__ u64 mul2(u64 a, u64 b) {
    u64 d; asm("mul.rn.f32x2 %0, %1, %2;" : "=l"(d) : "l"(a), "l"(b)); return d;
}
__device__ __forceinline__ void stg256_zero(void* p) {
    u32 z = 0u;
    asm volatile("st.global.v8.b32 [%0], {%1,%1,%1,%1,%1,%1,%1,%1};"
                 :: "l"(p), "r"(z) : "memory");
}
__device__ __forceinline__ void stg256f(void* p, float4 a, float4 b) {
    asm volatile("st.global.v8.b32 [%0], {%1,%2,%3,%4,%5,%6,%7,%8};"
                 :: "l"(p),
                    "r"(__float_as_uint(a.x)), "r"(__float_as_uint(a.y)),
                    "r"(__float_as_uint(a.z)), "r"(__float_as_uint(a.w)),
                    "r"(__float_as_uint(b.x)), "r"(__float_as_uint(b.y)),
                    "r"(__float_as_uint(b.z)), "r"(__float_as_uint(b.w))
                 : "memory");
}

// Per-row dots + local argmax; order identical to R3/R4/R11.
__device__ __forceinline__ void row_dots(const float* __restrict__ xrow,
                                         const u64 cc[4][8], int lane,
                                         float& best, int& bidx)
{
    const float4 xa = reinterpret_cast<const float4*>(xrow)[0];
    const float4 xb = reinterpret_cast<const float4*>(xrow)[1];
    u64 xx[8] = { pack2(xa.x, xa.x), pack2(xa.y, xa.y),
                  pack2(xa.z, xa.z), pack2(xa.w, xa.w),
                  pack2(xb.x, xb.x), pack2(xb.y, xb.y),
                  pack2(xb.z, xb.z), pack2(xb.w, xb.w) };
    best = -INFINITY;
    bidx = 0;
#pragma unroll
    for (int p = 0; p < 4; p++) {
        u64 acc = mul2(cc[p][0], xx[0]);
#pragma unroll
        for (int d = 1; d < 8; d++) acc = fma2(cc[p][d], xx[d], acc);
        float f0, f1; unpack2(acc, f0, f1);
        const int k0 = lane * 8 + 2 * p;
        if (f0 > best) { best = f0; bidx = k0;     }   // strict >: first-occ
        if (f1 > best) { best = f1; bidx = k0 + 1; }
    }
}

__device__ __forceinline__ int warp_argmax(float best, int bidx)
{
    u32 ord = __float_as_uint(best);
    ord = (ord & 0x80000000u) ? ~ord : (ord | 0x80000000u);
    const u32 mx   = __reduce_max_sync(0xffffffffu, ord);
    const u32 cand = (ord == mx) ? (u32)bidx : 0xFFFFFFFFu;
    return (int)__reduce_min_sync(0xffffffffu, cand);
}

__global__ __launch_bounds__(TILEB, 21)
void pq_fused_kernel(const float* __restrict__ x,
                     const float* __restrict__ C,
                     float* __restrict__ xhat,
                     float* __restrict__ codes)
{
    __shared__ float xs[TILEB * Dn];   // 1 KB x tile (this warp's 32 rows)

    const int m     = blockIdx.x;
    const int lane  = threadIdx.x & 31;
    const int tid   = threadIdx.x;
    const int btile = blockIdx.y * TILEB;

    // ---- Stage x tile: 32 rows x 32B, coalesced float4 loads (2 per thread,
    // each warp-instr touches 16 distinct 2KB-strided lines -> MLP=16).
#pragma unroll
    for (int pass = 0; pass < 2; pass++) {
        const int f    = pass * TILEB + tid;     // float4 id, 0..63
        const int row  = f >> 1;
        const int half = f & 1;
        reinterpret_cast<float4*>(xs)[f] = __ldg(reinterpret_cast<const float4*>(
            x + (size_t)(btile + row) * FEAT + m * Dn + half * 4));
    }

    // ---- Codebook cache: lane owns k = lane*8..+7, two codewords per f32x2.
    u64 cc[4][8];
    {
        const float4* Cm = reinterpret_cast<const float4*>(
            C + ((size_t)m * Kn + (size_t)lane * 8) * Dn);
#pragma unroll
        for (int p = 0; p < 4; p++) {
            float4 a0 = __ldg(Cm + 4 * p + 0);
            float4 a1 = __ldg(Cm + 4 * p + 1);
            float4 b0 = __ldg(Cm + 4 * p + 2);
            float4 b1 = __ldg(Cm + 4 * p + 3);
            cc[p][0] = pack2(a0.x, b0.x); cc[p][1] = pack2(a0.y, b0.y);
            cc[p][2] = pack2(a0.z, b0.z); cc[p][3] = pack2(a0.w, b0.w);
            cc[p][4] = pack2(a1.x, b1.x); cc[p][5] = pack2(a1.y, b1.y);
            cc[p][6] = pack2(a1.z, b1.z); cc[p][7] = pack2(a1.w, b1.w);
        }
    }
    __syncwarp();   // single-warp block: warp-level sync suffices for xs

    const float* xw    = xs;
    const int    brow0 = btile;
    float* crow = codes + ((size_t)brow0 * Mn + m) * Kn + (size_t)lane * 8;
    const size_t rstride = (size_t)Mn * Kn;

    for (int r = 0; r < RPW; r += 2) {
        // --- dots for the row pair (independent chains, compiler interleaves)
        float bestA, bestB; int idxA, idxB;
        row_dots(xw + (r + 0) * Dn, cc, lane, bestA, idxA);
        row_dots(xw + (r + 1) * Dn, cc, lane, bestB, idxB);

        // --- the two redux chains overlap their latency
        const int kA = warp_argmax(bestA, idxA);
        const int kB = warp_argmax(bestB, idxB);

        // --- stores, row A
        {
            const int b = brow0 + r;
            float* cp = crow;
            stg256_zero(cp);
            if ((kA >> 3) == lane) {
                // patch the 1.0 (same thread as the zero store -> ordered)
                *(cp + (kA & 7)) = 1.0f;
                const float4* cw = reinterpret_cast<const float4*>(
                    C + ((size_t)m * Kn + kA) * Dn);
                const float4 w0 = __ldg(cw);
                const float4 w1 = __ldg(cw + 1);
                stg256f(xhat + (size_t)b * FEAT + m * Dn, w0, w1);
            }
        }
        // --- stores, row B
        {
            const int b = brow0 + r + 1;
            float* cp = crow + rstride;
            stg256_zero(cp);
            if ((kB >> 3) == lane) {
                *(cp + (kB & 7)) = 1.0f;
                const float4* cw = reinterpret_cast<const float4*>(
                    C + ((size_t)m * Kn + kB) * Dn);
                const float4 w0 = __ldg(cw);
                const float4 w1 = __ldg(cw + 1);
                stg256f(xhat + (size_t)b * FEAT + m * Dn, w0, w1);
            }
        }
        crow += 2 * rstride;
    }
}

extern "C" void kernel_launch(void* const* d_in, const int* in_sizes, int n_in,
                              void* d_out, int out_size)
{
    // metadata order: x (B*FEAT), C (M*K*D). Defensive about ordering.
    const float* x = (const float*)d_in[0];
    const float* C = (const float*)d_in[1];
    if (in_sizes[0] == Mn * Kn * Dn && in_sizes[1] == Bn * FEAT) {
        x = (const float*)d_in[1];
        C = (const float*)d_in[0];
    }

    float* xhat  = (float*)d_out;
    float* codes = (float*)d_out + (size_t)Bn * FEAT;

    dim3 grid(Mn, Bn / TILEB);    // (64, 512)
    dim3 block(TILEB);            // 32 threads (1 warp)
    pq_fused_kernel<<<grid, block>>>(x, C, xhat, codes);
}

// round 16
// speedup vs baseline: 1.4501x; 1.4501x over previous
#include <cuda_runtime.h>
#include <math.h>

// PQLayer forward, fully fused (FINAL = R11, verified 206.6us / 206.8us):
//   per (b,m): k* = argmax_k <x[b,m*8:+8], C[m,k,:]>
//   codes[b,m,:] = one_hot(k*)   (exact forward value of straight-through:
//     (hard - soft) + soft == hard elementwise in IEEE fp32)
//   xhat[b,m*8:+8] = C[m,k*,:]
//
// Shapes: B=16384, FEAT=512, M=64, K=256, D=8.
// d_out: xhat (B*512 f32) then codes (B*M*K f32).
//
// Convergence record (all measured):
//   R1 510us naive fused | R2 461us split | R3 240us fused+f32x2+v8 stores
//   R4 209us zero-store+patch | R11 206.6us 64thr/10blk (96 regs, 20 warps/SM)
//   Dead ends: smem C & dup-x (229us, L1 contention), cross-iter pipeline
//   (226us), store hoist (neutral), 11x64 blocks (289us, cc spill),
//   21x32 blocks (299us, cc spill). Register floor = 96; occupancy optimum
//   = 20 warps/SM. Kernel runs at ~5.25TB/s on 1.14GB irreducible traffic,
//   ~97% of the chip's demonstrated write-stream ceiling. Converged.

#define Bn    16384
#define FEAT  512
#define Mn    64
#define Kn    256
#define Dn    8
#define WARPS 2
#define RPW   32
#define TILEB (WARPS * RPW)   // 64 rows per block

typedef unsigned long long u64;
typedef unsigned int u32;

__device__ __forceinline__ u64 pack2(float lo, float hi) {
    u64 r; asm("mov.b64 %0, {%1,%2};" : "=l"(r) : "f"(lo), "f"(hi)); return r;
}
__device__ __forceinline__ void unpack2(u64 v, float& lo, float& hi) {
    asm("mov.b64 {%0,%1}, %2;" : "=f"(lo), "=f"(hi) : "l"(v));
}
__device__ __forceinline__ u64 fma2(u64 a, u64 b, u64 c) {
    u64 d; asm("fma.rn.f32x2 %0, %1, %2, %3;" : "=l"(d) : "l"(a), "l"(b), "l"(c)); return d;
}
__device__ __forceinline__ u64 mul2(u64 a, u64 b) {
    u64 d; asm("mul.rn.f32x2 %0, %1, %2;" : "=l"(d) : "l"(a), "l"(b)); return d;
}
__device__ __forceinline__ void stg256_zero(void* p) {
    u32 z = 0u;
    asm volatile("st.global.v8.b32 [%0], {%1,%1,%1,%1,%1,%1,%1,%1};"
                 :: "l"(p), "r"(z) : "memory");
}
__device__ __forceinline__ void stg256f(void* p, float4 a, float4 b) {
    asm volatile("st.global.v8.b32 [%0], {%1,%2,%3,%4,%5,%6,%7,%8};"
                 :: "l"(p),
                    "r"(__float_as_uint(a.x)), "r"(__float_as_uint(a.y)),
                    "r"(__float_as_uint(a.z)), "r"(__float_as_uint(a.w)),
                    "r"(__float_as_uint(b.x)), "r"(__float_as_uint(b.y)),
                    "r"(__float_as_uint(b.z)), "r"(__float_as_uint(b.w))
                 : "memory");
}

// Per-row dots + local argmax; sequential-d summation order (rel_err 0.0 vs
// the reference every measured round).
__device__ __forceinline__ void row_dots(const float* __restrict__ xrow,
                                         const u64 cc[4][8], int lane,
                                         float& best, int& bidx)
{
    const float4 xa = reinterpret_cast<const float4*>(xrow)[0];
    const float4 xb = reinterpret_cast<const float4*>(xrow)[1];
    u64 xx[8] = { pack2(xa.x, xa.x), pack2(xa.y, xa.y),
                  pack2(xa.z, xa.z), pack2(xa.w, xa.w),
                  pack2(xb.x, xb.x), pack2(xb.y, xb.y),
                  pack2(xb.z, xb.z), pack2(xb.w, xb.w) };
    best = -INFINITY;
    bidx = 0;
#pragma unroll
    for (int p = 0; p < 4; p++) {
        u64 acc = mul2(cc[p][0], xx[0]);
#pragma unroll
        for (int d = 1; d < 8; d++) acc = fma2(cc[p][d], xx[d], acc);
        float f0, f1; unpack2(acc, f0, f1);
        const int k0 = lane * 8 + 2 * p;
        if (f0 > best) { best = f0; bidx = k0;     }   // strict >: first-occ
        if (f1 > best) { best = f1; bidx = k0 + 1; }
    }
}

// Warp argmax: redux max on order-preserving uint, then min index among tied
// lanes (lane order == k order -> jnp.argmax first-occurrence semantics).
__device__ __forceinline__ int warp_argmax(float best, int bidx)
{
    u32 ord = __float_as_uint(best);
    ord = (ord & 0x80000000u) ? ~ord : (ord | 0x80000000u);
    const u32 mx   = __reduce_max_sync(0xffffffffu, ord);
    const u32 cand = (ord == mx) ? (u32)bidx : 0xFFFFFFFFu;
    return (int)__reduce_min_sync(0xffffffffu, cand);
}

__global__ __launch_bounds__(TILEB, 10)
void pq_fused_kernel(const float* __restrict__ x,
                     const float* __restrict__ C,
                     float* __restrict__ xhat,
                     float* __restrict__ codes)
{
    __shared__ float xs[TILEB * Dn];   // 2 KB x tile

    const int m     = blockIdx.x;
    const int warp  = threadIdx.x >> 5;
    const int lane  = threadIdx.x & 31;
    const int tid   = threadIdx.x;
    const int btile = blockIdx.y * TILEB;

    // ---- Stage x tile (coalesced, MLP=16 per warp-instr).
#pragma unroll
    for (int pass = 0; pass < 2; pass++) {
        const int f    = pass * TILEB + tid;
        const int row  = f >> 1;
        const int half = f & 1;
        reinterpret_cast<float4*>(xs)[f] = __ldg(reinterpret_cast<const float4*>(
            x + (size_t)(btile + row) * FEAT + m * Dn + half * 4));
    }

    // ---- Codebook cache: lane owns k = lane*8..+7, two codewords per f32x2.
    u64 cc[4][8];
    {
        const float4* Cm = reinterpret_cast<const float4*>(
            C + ((size_t)m * Kn + (size_t)lane * 8) * Dn);
#pragma unroll
        for (int p = 0; p < 4; p++) {
            float4 a0 = __ldg(Cm + 4 * p + 0);
            float4 a1 = __ldg(Cm + 4 * p + 1);
            float4 b0 = __ldg(Cm + 4 * p + 2);
            float4 b1 = __ldg(Cm + 4 * p + 3);
            cc[p][0] = pack2(a0.x, b0.x); cc[p][1] = pack2(a0.y, b0.y);
            cc[p][2] = pack2(a0.z, b0.z); cc[p][3] = pack2(a0.w, b0.w);
            cc[p][4] = pack2(a1.x, b1.x); cc[p][5] = pack2(a1.y, b1.y);
            cc[p][6] = pack2(a1.z, b1.z); cc[p][7] = pack2(a1.w, b1.w);
        }
    }
    __syncthreads();

    const float* xw    = xs + warp * RPW * Dn;
    const int    brow0 = btile + warp * RPW;
    float* crow = codes + ((size_t)brow0 * Mn + m) * Kn + (size_t)lane * 8;
    const size_t rstride = (size_t)Mn * Kn;

    for (int r = 0; r < RPW; r += 2) {
        // --- dots for the row pair (independent chains, compiler interleaves)
        float bestA, bestB; int idxA, idxB;
        row_dots(xw + (r + 0) * Dn, cc, lane, bestA, idxA);
        row_dots(xw + (r + 1) * Dn, cc, lane, bestB, idxB);

        // --- the two redux chains overlap their latency
        const int kA = warp_argmax(bestA, idxA);
        const int kB = warp_argmax(bestB, idxB);

        // --- stores, row A
        {
            const int b = brow0 + r;
            float* cp = crow;
            stg256_zero(cp);
            if ((kA >> 3) == lane) {
                // patch the 1.0 (same thread as the zero store -> ordered)
                *(cp + (kA & 7)) = 1.0f;
                const float4* cw = reinterpret_cast<const float4*>(
                    C + ((size_t)m * Kn + kA) * Dn);
                const float4 w0 = __ldg(cw);
                const float4 w1 = __ldg(cw + 1);
                stg256f(xhat + (size_t)b * FEAT + m * Dn, w0, w1);
            }
        }
        // --- stores, row B
        {
            const int b = brow0 + r + 1;
            float* cp = crow + rstride;
            stg256_zero(cp);
            if ((kB >> 3) == lane) {
                *(cp + (kB & 7)) = 1.0f;
                const float4* cw = reinterpret_cast<const float4*>(
                    C + ((size_t)m * Kn + kB) * Dn);
                const float4 w0 = __ldg(cw);
                const float4 w1 = __ldg(cw + 1);
                stg256f(xhat + (size_t)b * FEAT + m * Dn, w0, w1);
            }
        }
        crow += 2 * rstride;
    }
}

extern "C" void kernel_launch(void* const* d_in, const int* in_sizes, int n_in,
                              void* d_out, int out_size)
{
    // metadata order: x (B*FEAT), C (M*K*D). Defensive about ordering.
    const float* x = (const float*)d_in[0];
    const float* C = (const float*)d_in[1];
    if (in_sizes[0] == Mn * Kn * Dn && in_sizes[1] == Bn * FEAT) {
        x = (const float*)d_in[1];
        C = (const float*)d_in[0];
    }

    float* xhat  = (float*)d_out;
    float* codes = (float*)d_out + (size_t)Bn * FEAT;

    dim3 grid(Mn, Bn / TILEB);    // (64, 256)
    dim3 block(TILEB);            // 64 threads (2 warps)
    pq_fused_kernel<<<grid, block>>>(x, C, xhat, codes);
}